// round 1
// baseline (speedup 1.0000x reference)
#include <cuda_runtime.h>

#define Bn 4096
#define Sn 64
#define Un 128
#define Mn 32
#define NUNF 6
#define EPSF 1e-8f
#define L2E 1.4426950408889634f

// ---- scratch (static device arrays; no allocation) ----
__device__ float g_A [Un*Un];   // -log2e * sigma
__device__ float g_Bc[Un*Un];   //  log2e * sigma * mu
__device__ float g_W [Un*Un];   //  w * mask * erev   (|g_W| = w*mask)
__device__ float g_As[Sn*Un];
__device__ float g_Bs[Sn*Un];
__device__ float g_Ws[Sn*Un];
__device__ float g_snum[Bn*Un];
__device__ float g_sden[Bn*Un];

// sigmoid(x) with t = -log2e*x already applied upstream:
// sig = 1 / (1 + 2^t)
__device__ __forceinline__ float fsig(float t) {
    float e; asm("ex2.approx.f32 %0, %1;" : "=f"(e) : "f"(t));
    float r; asm("rcp.approx.f32 %0, %1;" : "=f"(r) : "f"(1.0f + e));
    return r;
}

// ---- 1) fold constants ----
__global__ void prep_kernel(const float* __restrict__ sigma, const float* __restrict__ mu,
                            const float* __restrict__ w,     const float* __restrict__ erev,
                            const float* __restrict__ mask,
                            const float* __restrict__ ssig,  const float* __restrict__ smu,
                            const float* __restrict__ sw,    const float* __restrict__ serev,
                            const float* __restrict__ smask) {
    int i = blockIdx.x * 256 + threadIdx.x;
    if (i < Un*Un) {
        float s = sigma[i];
        g_A [i] = -L2E * s;
        g_Bc[i] =  L2E * s * mu[i];
        g_W [i] = w[i] * mask[i] * erev[i];
    }
    if (i < Sn*Un) {
        float s = ssig[i];
        g_As[i] = -L2E * s;
        g_Bs[i] =  L2E * s * smu[i];
        g_Ws[i] = sw[i] * smask[i] * serev[i];
    }
}

// ---- 2) sensory sums: one warp per batch, lane = 4 dst ----
__global__ __launch_bounds__(1024, 1) void sensory_kernel(
    const float* __restrict__ inputs, const float* __restrict__ inw,
    const float* __restrict__ inb) {
    int warp = threadIdx.x >> 5, lane = threadIdx.x & 31;
    int b = blockIdx.x * 32 + warp;
    const float4* A4 = (const float4*)g_As;
    const float4* B4 = (const float4*)g_Bs;
    const float4* W4 = (const float4*)g_Ws;
    float4 num = make_float4(0.f,0.f,0.f,0.f);
    float4 den = make_float4(0.f,0.f,0.f,0.f);
    #pragma unroll 4
    for (int s = 0; s < Sn; ++s) {
        float x = fmaf(__ldg(inputs + b*Sn + s), __ldg(inw + s), __ldg(inb + s));
        float4 a  = A4[s*32 + lane];
        float4 bb = B4[s*32 + lane];
        float4 we = W4[s*32 + lane];
        float r;
        r = fsig(fmaf(a.x, x, bb.x)); num.x = fmaf(r, we.x, num.x); den.x = fmaf(r, fabsf(we.x), den.x);
        r = fsig(fmaf(a.y, x, bb.y)); num.y = fmaf(r, we.y, num.y); den.y = fmaf(r, fabsf(we.y), den.y);
        r = fsig(fmaf(a.z, x, bb.z)); num.z = fmaf(r, we.z, num.z); den.z = fmaf(r, fabsf(we.z), den.z);
        r = fsig(fmaf(a.w, x, bb.w)); num.w = fmaf(r, we.w, num.w); den.w = fmaf(r, fabsf(we.w), den.w);
    }
    ((float4*)g_snum)[b*32 + lane] = num;
    ((float4*)g_sden)[b*32 + lane] = den;
}

// ---- 3) main ODE kernel ----
// 148 CTAs x 1024 threads. Recurrent weights (A,B,W) in SMEM (192KB).
// One warp per batch element; lane l owns dst 4l..4l+3; v state per warp in SMEM.
__global__ __launch_bounds__(1024, 1) void ltc_main(
    const float* __restrict__ state, const float* __restrict__ gleak,
    const float* __restrict__ vleak, const float* __restrict__ cm,
    const float* __restrict__ outw,  const float* __restrict__ outb,
    float* __restrict__ dout) {
    extern __shared__ float sm[];
    float4* sA = (float4*)sm;
    float4* sB = (float4*)(sm + Un*Un);
    float4* sW = (float4*)(sm + 2*Un*Un);
    float*  sV = sm + 3*Un*Un;          // 32 warps x 128 floats

    {   // cooperative SMEM fill (all warps, including ones with no batch)
        const float4* gA = (const float4*)g_A;
        const float4* gB = (const float4*)g_Bc;
        const float4* gW = (const float4*)g_W;
        for (int i = threadIdx.x; i < Un*Un/4; i += 1024) {
            sA[i] = gA[i]; sB[i] = gB[i]; sW[i] = gW[i];
        }
    }
    __syncthreads();

    int warp = threadIdx.x >> 5, lane = threadIdx.x & 31;
    int start = (int)(((long long)blockIdx.x       * Bn) / gridDim.x);
    int end   = (int)(((long long)(blockIdx.x + 1) * Bn) / gridDim.x);
    int b = start + warp;
    if (b >= end) return;

    int d0 = lane * 4;
    float4 cm4 = *(const float4*)(cm    + d0);
    float4 gl4 = *(const float4*)(gleak + d0);
    float4 vl4 = *(const float4*)(vleak + d0);
    float4 ns  = ((const float4*)g_snum)[b*32 + lane];
    float4 ds  = ((const float4*)g_sden)[b*32 + lane];

    float4 cmt;  cmt.x  = cm4.x * (float)NUNF; cmt.y = cm4.y * (float)NUNF;
                 cmt.z  = cm4.z * (float)NUNF; cmt.w = cm4.w * (float)NUNF;
    float4 num0; num0.x = fmaf(gl4.x, vl4.x, ns.x); num0.y = fmaf(gl4.y, vl4.y, ns.y);
                 num0.z = fmaf(gl4.z, vl4.z, ns.z); num0.w = fmaf(gl4.w, vl4.w, ns.w);
    float4 den0; den0.x = cmt.x + gl4.x + EPSF + ds.x; den0.y = cmt.y + gl4.y + EPSF + ds.y;
                 den0.z = cmt.z + gl4.z + EPSF + ds.z; den0.w = cmt.w + gl4.w + EPSF + ds.w;

    float4 v = *(const float4*)(state + b*Un + d0);
    ((float4*)(sV + warp*Un))[lane] = v;
    __syncwarp();

    const float* vp = sV + warp*Un;
    for (int it = 0; it < NUNF; ++it) {
        float4 num = num0, den = den0;
        #pragma unroll 2
        for (int s = 0; s < Un; ++s) {
            float vs  = vp[s];                    // warp broadcast
            float4 a  = sA[s*32 + lane];
            float4 bb = sB[s*32 + lane];
            float4 we = sW[s*32 + lane];
            float r;
            r = fsig(fmaf(a.x, vs, bb.x)); num.x = fmaf(r, we.x, num.x); den.x = fmaf(r, fabsf(we.x), den.x);
            r = fsig(fmaf(a.y, vs, bb.y)); num.y = fmaf(r, we.y, num.y); den.y = fmaf(r, fabsf(we.y), den.y);
            r = fsig(fmaf(a.z, vs, bb.z)); num.z = fmaf(r, we.z, num.z); den.z = fmaf(r, fabsf(we.z), den.z);
            r = fsig(fmaf(a.w, vs, bb.w)); num.w = fmaf(r, we.w, num.w); den.w = fmaf(r, fabsf(we.w), den.w);
        }
        float4 vn;
        vn.x = fmaf(cmt.x, v.x, num.x) / den.x;
        vn.y = fmaf(cmt.y, v.y, num.y) / den.y;
        vn.z = fmaf(cmt.z, v.z, num.z) / den.z;
        vn.w = fmaf(cmt.w, v.w, num.w) / den.w;
        __syncwarp();                              // all lanes done reading old v
        ((float4*)(sV + warp*Un))[lane] = vn;
        __syncwarp();                              // new v visible to all lanes
        v = vn;
    }

    // v section of output: [B*M, B*M + B*U)
    ((float4*)(dout + Bn*Mn + b*Un))[lane] = v;
    // motor output: out = v[:, :M]*output_w + output_b
    if (d0 < Mn) {
        float4 ow = *(const float4*)(outw + d0);
        float4 ob = *(const float4*)(outb + d0);
        float4 o;
        o.x = fmaf(v.x, ow.x, ob.x); o.y = fmaf(v.y, ow.y, ob.y);
        o.z = fmaf(v.z, ow.z, ob.z); o.w = fmaf(v.w, ow.w, ob.w);
        ((float4*)(dout + b*Mn))[lane] = o;
    }
}

extern "C" void kernel_launch(void* const* d_in, const int* in_sizes, int n_in,
                              void* d_out, int out_size) {
    const float* inputs = (const float*)d_in[0];
    const float* state  = (const float*)d_in[1];
    const float* gleak  = (const float*)d_in[2];
    const float* vleak  = (const float*)d_in[3];
    const float* cm     = (const float*)d_in[4];
    const float* sigma  = (const float*)d_in[5];
    const float* mu     = (const float*)d_in[6];
    const float* w      = (const float*)d_in[7];
    const float* erev   = (const float*)d_in[8];
    const float* ssig   = (const float*)d_in[9];
    const float* smu    = (const float*)d_in[10];
    const float* sw     = (const float*)d_in[11];
    const float* serev  = (const float*)d_in[12];
    const float* mask   = (const float*)d_in[13];
    const float* smask  = (const float*)d_in[14];
    const float* inw    = (const float*)d_in[15];
    const float* inb    = (const float*)d_in[16];
    const float* outw   = (const float*)d_in[17];
    const float* outb   = (const float*)d_in[18];
    float* out = (float*)d_out;

    prep_kernel<<<64, 256>>>(sigma, mu, w, erev, mask, ssig, smu, sw, serev, smask);
    sensory_kernel<<<Bn/32, 1024>>>(inputs, inw, inb);

    size_t shmem = (size_t)(3*Un*Un + 32*Un) * sizeof(float);   // 208 KB
    cudaFuncSetAttribute(ltc_main, cudaFuncAttributeMaxDynamicSharedMemorySize, (int)shmem);
    ltc_main<<<148, 1024, shmem>>>(state, gleak, vleak, cm, outw, outb, out);
}

// round 2
// speedup vs baseline: 1.5953x; 1.5953x over previous
#include <cuda_runtime.h>

#define Bn 4096
#define Sn 64
#define Un 128
#define Mn 32
#define NUNF 6
#define EPSF 1e-8f

// ---- scratch (static device arrays; no allocation) ----
// sigmoid(sig*(v-mu)) = 0.5 + 0.5*tanh(0.5*sig*v - 0.5*sig*mu)
__device__ float g_A [Un*Un];   //  0.5*sigma
__device__ float g_Bc[Un*Un];   // -0.5*sigma*mu
__device__ float g_W [Un*Un];   //  0.5*w*mask*erev   (|g_W| = 0.5*w*mask)
__device__ float g_As[Sn*Un];
__device__ float g_Bs[Sn*Un];
__device__ float g_Ws[Sn*Un];
__device__ float g_nbase[Un];   // leak + 0.5*col-sums of W (rec + sensory)
__device__ float g_dbase[Un];   // cm*6 + gleak + eps + 0.5*col-sums of |W|
__device__ float g_snum[Bn*Un]; // sensory tanh-weighted sums
__device__ float g_sden[Bn*Un];

__device__ __forceinline__ float ftanh(float x) {
    float t; asm("tanh.approx.f32 %0, %1;" : "=f"(t) : "f"(x));
    return t;
}

// ---- 1) fold constants ----
__global__ void prep_kernel(const float* __restrict__ sigma, const float* __restrict__ mu,
                            const float* __restrict__ w,     const float* __restrict__ erev,
                            const float* __restrict__ mask,
                            const float* __restrict__ ssig,  const float* __restrict__ smu,
                            const float* __restrict__ sw,    const float* __restrict__ serev,
                            const float* __restrict__ smask) {
    int i = blockIdx.x * 256 + threadIdx.x;
    if (i < Un*Un) {
        float s = 0.5f * sigma[i];
        g_A [i] = s;
        g_Bc[i] = -s * mu[i];
        g_W [i] = 0.5f * w[i] * mask[i] * erev[i];
    }
    if (i < Sn*Un) {
        float s = 0.5f * ssig[i];
        g_As[i] = s;
        g_Bs[i] = -s * smu[i];
        g_Ws[i] = 0.5f * sw[i] * smask[i] * serev[i];
    }
}

// ---- 1b) per-dst constant bases (runs after prep) ----
__global__ void base_kernel(const float* __restrict__ gleak, const float* __restrict__ vleak,
                            const float* __restrict__ cm) {
    int d = threadIdx.x;
    if (d >= Un) return;
    float nb = gleak[d] * vleak[d];
    float db = cm[d] * (float)NUNF + gleak[d] + EPSF;
    #pragma unroll 8
    for (int s = 0; s < Un; ++s) {
        float wv = g_W[s*Un + d];
        nb += wv; db += fabsf(wv);
    }
    #pragma unroll 8
    for (int s = 0; s < Sn; ++s) {
        float wv = g_Ws[s*Un + d];
        nb += wv; db += fabsf(wv);
    }
    g_nbase[d] = nb;
    g_dbase[d] = db;
}

// ---- 2) sensory tanh sums: one warp per batch, lane = 4 dst ----
__global__ __launch_bounds__(1024, 1) void sensory_kernel(
    const float* __restrict__ inputs, const float* __restrict__ inw,
    const float* __restrict__ inb) {
    int warp = threadIdx.x >> 5, lane = threadIdx.x & 31;
    int b = blockIdx.x * 32 + warp;
    const float4* A4 = (const float4*)g_As;
    const float4* B4 = (const float4*)g_Bs;
    const float4* W4 = (const float4*)g_Ws;
    float4 num = make_float4(0.f,0.f,0.f,0.f);
    float4 den = make_float4(0.f,0.f,0.f,0.f);
    #pragma unroll 4
    for (int s = 0; s < Sn; ++s) {
        float x = fmaf(__ldg(inputs + b*Sn + s), __ldg(inw + s), __ldg(inb + s));
        float4 a  = A4[s*32 + lane];
        float4 bb = B4[s*32 + lane];
        float4 we = W4[s*32 + lane];
        float t;
        t = ftanh(fmaf(a.x, x, bb.x)); num.x = fmaf(t, we.x, num.x); den.x = fmaf(t, fabsf(we.x), den.x);
        t = ftanh(fmaf(a.y, x, bb.y)); num.y = fmaf(t, we.y, num.y); den.y = fmaf(t, fabsf(we.y), den.y);
        t = ftanh(fmaf(a.z, x, bb.z)); num.z = fmaf(t, we.z, num.z); den.z = fmaf(t, fabsf(we.z), den.z);
        t = ftanh(fmaf(a.w, x, bb.w)); num.w = fmaf(t, we.w, num.w); den.w = fmaf(t, fabsf(we.w), den.w);
    }
    ((float4*)g_snum)[b*32 + lane] = num;
    ((float4*)g_sden)[b*32 + lane] = den;
}

// ---- 3) main ODE kernel ----
// 148 CTAs x 448 threads (14 warps). Each warp handles 2 batch elements,
// sharing each weight load. lane owns dst 4*lane..4*lane+3.
#define NWARP 14
__global__ __launch_bounds__(NWARP*32, 1) void ltc_main(
    const float* __restrict__ state, const float* __restrict__ cm,
    const float* __restrict__ outw,  const float* __restrict__ outb,
    float* __restrict__ dout) {
    extern __shared__ float sm[];
    float4* sA = (float4*)sm;
    float4* sB = (float4*)(sm + Un*Un);
    float4* sW = (float4*)(sm + 2*Un*Un);
    float*  sV = sm + 3*Un*Un;          // NWARP warps x 2 batches x 128 floats

    {   // cooperative SMEM fill
        const float4* gA = (const float4*)g_A;
        const float4* gB = (const float4*)g_Bc;
        const float4* gW = (const float4*)g_W;
        for (int i = threadIdx.x; i < Un*Un/4; i += NWARP*32) {
            sA[i] = gA[i]; sB[i] = gB[i]; sW[i] = gW[i];
        }
    }
    __syncthreads();

    int warp = threadIdx.x >> 5, lane = threadIdx.x & 31;
    int start = (int)(((long long)blockIdx.x       * Bn) / gridDim.x);
    int end   = (int)(((long long)(blockIdx.x + 1) * Bn) / gridDim.x);
    int b0 = start + warp * 2;
    if (b0 >= end) return;
    int b1 = (b0 + 1 < end) ? (b0 + 1) : b0;   // duplicate work if odd tail
    bool has1 = (b0 + 1 < end);

    int d0 = lane * 4;
    float4 cm4  = *(const float4*)(cm      + d0);
    float4 nb4  = *(const float4*)(g_nbase + d0);
    float4 db4  = *(const float4*)(g_dbase + d0);
    float4 cmt;  cmt.x = cm4.x * (float)NUNF; cmt.y = cm4.y * (float)NUNF;
                 cmt.z = cm4.z * (float)NUNF; cmt.w = cm4.w * (float)NUNF;

    float4 sn0 = ((const float4*)g_snum)[b0*32 + lane];
    float4 sd0 = ((const float4*)g_sden)[b0*32 + lane];
    float4 sn1 = ((const float4*)g_snum)[b1*32 + lane];
    float4 sd1 = ((const float4*)g_sden)[b1*32 + lane];
    float4 nA, dA, nB, dB;
    nA.x = nb4.x + sn0.x; nA.y = nb4.y + sn0.y; nA.z = nb4.z + sn0.z; nA.w = nb4.w + sn0.w;
    dA.x = db4.x + sd0.x; dA.y = db4.y + sd0.y; dA.z = db4.z + sd0.z; dA.w = db4.w + sd0.w;
    nB.x = nb4.x + sn1.x; nB.y = nb4.y + sn1.y; nB.z = nb4.z + sn1.z; nB.w = nb4.w + sn1.w;
    dB.x = db4.x + sd1.x; dB.y = db4.y + sd1.y; dB.z = db4.z + sd1.z; dB.w = db4.w + sd1.w;

    float4 v0 = *(const float4*)(state + b0*Un + d0);
    float4 v1 = *(const float4*)(state + b1*Un + d0);
    float* vp0 = sV + (warp*2 + 0)*Un;
    float* vp1 = sV + (warp*2 + 1)*Un;
    ((float4*)vp0)[lane] = v0;
    ((float4*)vp1)[lane] = v1;
    __syncwarp();

    for (int it = 0; it < NUNF; ++it) {
        float4 num0 = nA, den0 = dA, num1 = nB, den1 = dB;
        #pragma unroll 2
        for (int s = 0; s < Un; ++s) {
            float vs0 = vp0[s];
            float vs1 = vp1[s];
            float4 a  = sA[s*32 + lane];
            float4 bb = sB[s*32 + lane];
            float4 we = sW[s*32 + lane];
            float wax = fabsf(we.x), way = fabsf(we.y), waz = fabsf(we.z), waw = fabsf(we.w);
            float t;
            t = ftanh(fmaf(a.x, vs0, bb.x)); num0.x = fmaf(t, we.x, num0.x); den0.x = fmaf(t, wax, den0.x);
            t = ftanh(fmaf(a.y, vs0, bb.y)); num0.y = fmaf(t, we.y, num0.y); den0.y = fmaf(t, way, den0.y);
            t = ftanh(fmaf(a.z, vs0, bb.z)); num0.z = fmaf(t, we.z, num0.z); den0.z = fmaf(t, waz, den0.z);
            t = ftanh(fmaf(a.w, vs0, bb.w)); num0.w = fmaf(t, we.w, num0.w); den0.w = fmaf(t, waw, den0.w);
            t = ftanh(fmaf(a.x, vs1, bb.x)); num1.x = fmaf(t, we.x, num1.x); den1.x = fmaf(t, wax, den1.x);
            t = ftanh(fmaf(a.y, vs1, bb.y)); num1.y = fmaf(t, we.y, num1.y); den1.y = fmaf(t, way, den1.y);
            t = ftanh(fmaf(a.z, vs1, bb.z)); num1.z = fmaf(t, we.z, num1.z); den1.z = fmaf(t, waz, den1.z);
            t = ftanh(fmaf(a.w, vs1, bb.w)); num1.w = fmaf(t, we.w, num1.w); den1.w = fmaf(t, waw, den1.w);
        }
        float4 vn0, vn1;
        vn0.x = fmaf(cmt.x, v0.x, num0.x) / den0.x;
        vn0.y = fmaf(cmt.y, v0.y, num0.y) / den0.y;
        vn0.z = fmaf(cmt.z, v0.z, num0.z) / den0.z;
        vn0.w = fmaf(cmt.w, v0.w, num0.w) / den0.w;
        vn1.x = fmaf(cmt.x, v1.x, num1.x) / den1.x;
        vn1.y = fmaf(cmt.y, v1.y, num1.y) / den1.y;
        vn1.z = fmaf(cmt.z, v1.z, num1.z) / den1.z;
        vn1.w = fmaf(cmt.w, v1.w, num1.w) / den1.w;
        __syncwarp();
        ((float4*)vp0)[lane] = vn0;
        ((float4*)vp1)[lane] = vn1;
        __syncwarp();
        v0 = vn0; v1 = vn1;
    }

    // v section of output: [B*M, B*M + B*U)
    ((float4*)(dout + Bn*Mn + b0*Un))[lane] = v0;
    if (has1) ((float4*)(dout + Bn*Mn + b1*Un))[lane] = v1;
    // motor output: out = v[:, :M]*output_w + output_b
    if (d0 < Mn) {
        float4 ow = *(const float4*)(outw + d0);
        float4 ob = *(const float4*)(outb + d0);
        float4 o;
        o.x = fmaf(v0.x, ow.x, ob.x); o.y = fmaf(v0.y, ow.y, ob.y);
        o.z = fmaf(v0.z, ow.z, ob.z); o.w = fmaf(v0.w, ow.w, ob.w);
        ((float4*)(dout + b0*Mn))[lane] = o;
        if (has1) {
            o.x = fmaf(v1.x, ow.x, ob.x); o.y = fmaf(v1.y, ow.y, ob.y);
            o.z = fmaf(v1.z, ow.z, ob.z); o.w = fmaf(v1.w, ow.w, ob.w);
            ((float4*)(dout + b1*Mn))[lane] = o;
        }
    }
}

extern "C" void kernel_launch(void* const* d_in, const int* in_sizes, int n_in,
                              void* d_out, int out_size) {
    const float* inputs = (const float*)d_in[0];
    const float* state  = (const float*)d_in[1];
    const float* gleak  = (const float*)d_in[2];
    const float* vleak  = (const float*)d_in[3];
    const float* cm     = (const float*)d_in[4];
    const float* sigma  = (const float*)d_in[5];
    const float* mu     = (const float*)d_in[6];
    const float* w      = (const float*)d_in[7];
    const float* erev   = (const float*)d_in[8];
    const float* ssig   = (const float*)d_in[9];
    const float* smu    = (const float*)d_in[10];
    const float* sw     = (const float*)d_in[11];
    const float* serev  = (const float*)d_in[12];
    const float* mask   = (const float*)d_in[13];
    const float* smask  = (const float*)d_in[14];
    const float* inw    = (const float*)d_in[15];
    const float* inb    = (const float*)d_in[16];
    const float* outw   = (const float*)d_in[17];
    const float* outb   = (const float*)d_in[18];
    float* out = (float*)d_out;

    prep_kernel<<<64, 256>>>(sigma, mu, w, erev, mask, ssig, smu, sw, serev, smask);
    base_kernel<<<1, Un>>>(gleak, vleak, cm);
    sensory_kernel<<<Bn/32, 1024>>>(inputs, inw, inb);

    size_t shmem = (size_t)(3*Un*Un + NWARP*2*Un) * sizeof(float);   // 192KB + 14KB
    cudaFuncSetAttribute(ltc_main, cudaFuncAttributeMaxDynamicSharedMemorySize, (int)shmem);
    ltc_main<<<148, NWARP*32, shmem>>>(state, cm, outw, outb, out);
}